// round 10
// baseline (speedup 1.0000x reference)
#include <cuda_runtime.h>
#include <cstdint>

// Output: [1024, 201000] fp32 = one_hot(h,1e5) ++ one_hot(r,1e3) ++ one_hot(t,1e5).
// Persistent grid-stride kernel: one wave of CTAs loops over row-tiles,
// eliminating wave-tail imbalance. Fast path = dense STG.128 zero bursts with
// a block-uniform hot-column check.

static constexpr int BATCH = 1024;
static constexpr int ENTITIES_N = 100000;
static constexpr int RELATIONS_N = 1000;
static constexpr int WIDTH = ENTITIES_N * 2 + RELATIONS_N;  // 201000 floats
static constexpr int WIDTH4 = WIDTH / 4;                    // 50250 float4s
static constexpr int THREADS = 256;
static constexpr int F4_PER_THREAD = 8;
static constexpr int F4_PER_TILE = THREADS * F4_PER_THREAD;                      // 2048
static constexpr int TILES_PER_ROW = (WIDTH4 + F4_PER_TILE - 1) / F4_PER_TILE;   // 25
static constexpr int TOTAL_TILES = TILES_PER_ROW * BATCH;                        // 25600
static constexpr int SMS = 148;
static constexpr int CTAS_PER_SM = 8;   // 256 thr, 22 regs -> thread-limited at 8
static constexpr int GRID = SMS * CTAS_PER_SM;                                   // 1184

__global__ void __launch_bounds__(THREADS) onehot_kernel(
    float4* __restrict__ out,
    const int* __restrict__ hID,
    const int* __restrict__ rID,
    const int* __restrict__ tID) {

    const int tid = threadIdx.x;
    const float4 z = make_float4(0.f, 0.f, 0.f, 0.f);

    for (int tile = blockIdx.x; tile < TOTAL_TILES; tile += gridDim.x) {
        const int row = tile / TILES_PER_ROW;       // const-div -> IMAD sequence
        const int blk = tile - row * TILES_PER_ROW;
        const int base4 = blk * F4_PER_TILE;        // first float4 of this tile (within row)

        // Hot columns for this row (float indices). Broadcast loads -> L1/L2 hits.
        const int c0 = __ldg(hID + row);
        const int c1 = ENTITIES_N + __ldg(rID + row);
        const int c2 = ENTITIES_N + RELATIONS_N + __ldg(tID + row);

        const int lo = base4 * 4;
        const int hi = lo + F4_PER_TILE * 4;

        float4* p = out + (long long)row * WIDTH4 + base4 + tid;

        // Block-uniform conditions.
        const bool hot = (c0 >= lo && c0 < hi) || (c1 >= lo && c1 < hi) || (c2 >= lo && c2 < hi);
        const bool full = (base4 + F4_PER_TILE <= WIDTH4);   // all but last tile per row

        if (!hot && full) {
            // Fast path (~87% of tiles): dense STG.128 zeros, no per-element ALU.
            #pragma unroll
            for (int k = 0; k < F4_PER_THREAD; k++) {
                __stcs(p + k * THREADS, z);
            }
        } else {
            // Hot and/or tail tile: per-element compares + bounds.
            #pragma unroll
            for (int k = 0; k < F4_PER_THREAD; k++) {
                const int i4 = base4 + k * THREADS + tid;
                if (i4 < WIDTH4) {
                    const int b = i4 * 4;
                    float4 v;
                    v.x = (b + 0 == c0 || b + 0 == c1 || b + 0 == c2) ? 1.f : 0.f;
                    v.y = (b + 1 == c0 || b + 1 == c1 || b + 1 == c2) ? 1.f : 0.f;
                    v.z = (b + 2 == c0 || b + 2 == c1 || b + 2 == c2) ? 1.f : 0.f;
                    v.w = (b + 3 == c0 || b + 3 == c1 || b + 3 == c2) ? 1.f : 0.f;
                    __stcs(p + k * THREADS, v);
                }
            }
        }
    }
}

extern "C" void kernel_launch(void* const* d_in, const int* in_sizes, int n_in,
                              void* d_out, int out_size) {
    // inputs: z (float32, unused), hID (int32), rID (int32), tID (int32)
    const int* hID = (const int*)d_in[1];
    const int* rID = (const int*)d_in[2];
    const int* tID = (const int*)d_in[3];

    onehot_kernel<<<GRID, THREADS>>>((float4*)d_out, hID, rID, tID);
}

// round 11
// speedup vs baseline: 1.1655x; 1.1655x over previous
#include <cuda_runtime.h>
#include <cstdint>

// Output: [1024, 201000] fp32 = one_hot(h,1e5) ++ one_hot(r,1e3) ++ one_hot(t,1e5).
// Store-first strategy: every block unconditionally issues its dense STG.128
// zero burst (independent of the index loads), then the owning thread
// overwrites hot elements with 1.0f. Same-thread same-address stores are
// program-ordered, so no branch/stall sits in front of the store stream.

static constexpr int BATCH = 1024;
static constexpr int ENTITIES_N = 100000;
static constexpr int RELATIONS_N = 1000;
static constexpr int WIDTH = ENTITIES_N * 2 + RELATIONS_N;  // 201000 floats
static constexpr int WIDTH4 = WIDTH / 4;                    // 50250 float4s
static constexpr int THREADS = 256;
static constexpr int F4_PER_THREAD = 8;
static constexpr int F4_PER_BLOCK = THREADS * F4_PER_THREAD;                       // 2048
static constexpr int BLOCKS_PER_ROW = (WIDTH4 + F4_PER_BLOCK - 1) / F4_PER_BLOCK;  // 25

__global__ void __launch_bounds__(THREADS) onehot_kernel(
    float* __restrict__ outf,
    const int* __restrict__ hID,
    const int* __restrict__ rID,
    const int* __restrict__ tID) {

    const int row = blockIdx.y;
    const int blk = blockIdx.x;
    const int tid = threadIdx.x;
    const int base4 = blk * F4_PER_BLOCK;   // first float4 index of this block (within row)

    // Kick off the (broadcast) index loads early; nothing below the zero burst
    // depends on them, so the burst issues immediately.
    const int h = __ldg(hID + row);
    const int r = __ldg(rID + row);
    const int t = __ldg(tID + row);

    float* rowp = outf + (long long)row * WIDTH;
    float4* p = (float4*)rowp + base4 + tid;
    const float4 z = make_float4(0.f, 0.f, 0.f, 0.f);

    const bool full = (base4 + F4_PER_BLOCK <= WIDTH4);   // block-uniform

    // ── Phase 1: unconditional zero burst (branch-free for full blocks) ──
    if (full) {
        #pragma unroll
        for (int k = 0; k < F4_PER_THREAD; k++) {
            __stcs(p + k * THREADS, z);
        }
    } else {
        #pragma unroll
        for (int k = 0; k < F4_PER_THREAD; k++) {
            if (base4 + k * THREADS + tid < WIDTH4) __stcs(p + k * THREADS, z);
        }
    }

    // ── Phase 2: hot-element fixup by the owning thread (ordered after its
    //            own zero store to the same address) ──
    const int lo = base4 * 4;                 // float range covered by this block
    const int hi = lo + F4_PER_BLOCK * 4;

    const int c0 = h;
    const int c1 = ENTITIES_N + r;
    const int c2 = ENTITIES_N + RELATIONS_N + t;

    #pragma unroll
    for (int j = 0; j < 3; j++) {
        const int c = (j == 0) ? c0 : (j == 1) ? c1 : c2;
        if (c >= lo && c < hi) {
            const int pos4 = (c >> 2) - base4;        // float4 slot within block
            // layout: slot = k*THREADS + tid  ->  owner tid = pos4 % THREADS
            if ((pos4 & (THREADS - 1)) == tid) {
                rowp[c] = 1.0f;                        // same thread that zeroed it
            }
        }
    }
}

extern "C" void kernel_launch(void* const* d_in, const int* in_sizes, int n_in,
                              void* d_out, int out_size) {
    // inputs: z (float32, unused), hID (int32), rID (int32), tID (int32)
    const int* hID = (const int*)d_in[1];
    const int* rID = (const int*)d_in[2];
    const int* tID = (const int*)d_in[3];

    dim3 grid(BLOCKS_PER_ROW, BATCH, 1);
    onehot_kernel<<<grid, THREADS>>>((float*)d_out, hID, rID, tID);
}

// round 12
// speedup vs baseline: 1.1729x; 1.0064x over previous
#include <cuda_runtime.h>
#include <cstdint>

// Output: [1024, 201000] fp32 = one_hot(h,1e5) ++ one_hot(r,1e3) ++ one_hot(t,1e5).
// Store-first strategy (round-11 best structure): every block unconditionally
// issues its dense STG.128 zero burst, then the owning thread overwrites the
// hot elements with 1.0f (same-thread stores are program-ordered).
// This round: 512 threads/block, 4 float4/thread — same 2048-f4 block
// footprint, 2x independent store streams per block.

static constexpr int BATCH = 1024;
static constexpr int ENTITIES_N = 100000;
static constexpr int RELATIONS_N = 1000;
static constexpr int WIDTH = ENTITIES_N * 2 + RELATIONS_N;  // 201000 floats
static constexpr int WIDTH4 = WIDTH / 4;                    // 50250 float4s
static constexpr int THREADS = 512;
static constexpr int F4_PER_THREAD = 4;
static constexpr int F4_PER_BLOCK = THREADS * F4_PER_THREAD;                       // 2048
static constexpr int BLOCKS_PER_ROW = (WIDTH4 + F4_PER_BLOCK - 1) / F4_PER_BLOCK;  // 25

__global__ void __launch_bounds__(THREADS) onehot_kernel(
    float* __restrict__ outf,
    const int* __restrict__ hID,
    const int* __restrict__ rID,
    const int* __restrict__ tID) {

    const int row = blockIdx.y;
    const int blk = blockIdx.x;
    const int tid = threadIdx.x;
    const int base4 = blk * F4_PER_BLOCK;   // first float4 index of this block (within row)

    // Kick off the (broadcast) index loads early; the zero burst below does
    // not depend on them, so it issues immediately.
    const int h = __ldg(hID + row);
    const int r = __ldg(rID + row);
    const int t = __ldg(tID + row);

    float* rowp = outf + (long long)row * WIDTH;
    float4* p = (float4*)rowp + base4 + tid;
    const float4 z = make_float4(0.f, 0.f, 0.f, 0.f);

    const bool full = (base4 + F4_PER_BLOCK <= WIDTH4);   // block-uniform

    // ── Phase 1: unconditional zero burst (branch-free for full blocks) ──
    if (full) {
        #pragma unroll
        for (int k = 0; k < F4_PER_THREAD; k++) {
            __stcs(p + k * THREADS, z);
        }
    } else {
        #pragma unroll
        for (int k = 0; k < F4_PER_THREAD; k++) {
            if (base4 + k * THREADS + tid < WIDTH4) __stcs(p + k * THREADS, z);
        }
    }

    // ── Phase 2: hot-element fixup by the owning thread (program-ordered
    //            after that thread's zero store to the same address) ──
    const int lo = base4 * 4;
    const int hi = lo + F4_PER_BLOCK * 4;

    const int c0 = h;
    const int c1 = ENTITIES_N + r;
    const int c2 = ENTITIES_N + RELATIONS_N + t;

    #pragma unroll
    for (int j = 0; j < 3; j++) {
        const int c = (j == 0) ? c0 : (j == 1) ? c1 : c2;
        if (c >= lo && c < hi) {
            const int pos4 = (c >> 2) - base4;        // float4 slot within block
            // layout: slot = k*THREADS + tid  ->  owner tid = pos4 % THREADS
            if ((pos4 & (THREADS - 1)) == tid) {
                rowp[c] = 1.0f;
            }
        }
    }
}

extern "C" void kernel_launch(void* const* d_in, const int* in_sizes, int n_in,
                              void* d_out, int out_size) {
    // inputs: z (float32, unused), hID (int32), rID (int32), tID (int32)
    const int* hID = (const int*)d_in[1];
    const int* rID = (const int*)d_in[2];
    const int* tID = (const int*)d_in[3];

    dim3 grid(BLOCKS_PER_ROW, BATCH, 1);
    onehot_kernel<<<grid, THREADS>>>((float*)d_out, hID, rID, tID);
}

// round 13
// speedup vs baseline: 1.1811x; 1.0070x over previous
#include <cuda_runtime.h>
#include <cstdint>

// Output: [1024, 201000] fp32 = one_hot(h,1e5) ++ one_hot(r,1e3) ++ one_hot(t,1e5).
// Flattened 1-D store-first kernel: TOTAL4 = 51,456,000 float4s divides exactly
// into 25125 blocks x 2048 float4s -> every block is full and branch-free.
// Phase 1: unconditional dense STG.128 zero burst.
// Phase 2: owning thread overwrites hot elements with 1.0f (same-thread stores
// to the same address are program-ordered; a block spans at most 2 rows).

static constexpr int BATCH = 1024;
static constexpr int ENTITIES_N = 100000;
static constexpr int RELATIONS_N = 1000;
static constexpr int WIDTH = ENTITIES_N * 2 + RELATIONS_N;   // 201000 floats/row
static constexpr long long TOTAL = (long long)BATCH * WIDTH; // 205,824,000 floats
static constexpr int TOTAL4 = (int)(TOTAL / 4);              // 51,456,000 float4s
static constexpr int THREADS = 512;
static constexpr int F4_PER_THREAD = 4;
static constexpr int F4_PER_BLOCK = THREADS * F4_PER_THREAD; // 2048
static constexpr int NBLOCKS = TOTAL4 / F4_PER_BLOCK;        // 25125, exact
static_assert(NBLOCKS * F4_PER_BLOCK == TOTAL4, "grid must divide exactly");

__global__ void __launch_bounds__(THREADS) onehot_kernel(
    float* __restrict__ outf,
    const int* __restrict__ hID,
    const int* __restrict__ rID,
    const int* __restrict__ tID) {

    const int tid = threadIdx.x;
    const int base4 = blockIdx.x * F4_PER_BLOCK;   // global float4 index of block start
    const int lo = base4 * 4;                      // global float range of block
    const int hi = lo + F4_PER_BLOCK * 4;          // (8192 floats, < WIDTH)

    float4* p = (float4*)outf + base4 + tid;
    const float4 z = make_float4(0.f, 0.f, 0.f, 0.f);

    // ── Phase 1: branch-free dense zero burst (every block is full) ──
    #pragma unroll
    for (int k = 0; k < F4_PER_THREAD; k++) {
        __stcs(p + k * THREADS, z);
    }

    // ── Phase 2: hot-element fixup for the (at most 2) rows this block spans ──
    const int row0 = lo / WIDTH;
    const int row1 = (hi - 1) / WIDTH;

    #pragma unroll 1
    for (int row = row0; row <= row1; row++) {
        const int rs = row * WIDTH;                // row start (global float index)
        const int c0 = rs + __ldg(hID + row);
        const int c1 = rs + ENTITIES_N + __ldg(rID + row);
        const int c2 = rs + ENTITIES_N + RELATIONS_N + __ldg(tID + row);

        #pragma unroll
        for (int j = 0; j < 3; j++) {
            const int c = (j == 0) ? c0 : (j == 1) ? c1 : c2;
            if (c >= lo && c < hi) {
                const int pos4 = (c >> 2) - base4;          // float4 slot within block
                // layout: slot = k*THREADS + tid -> owner tid = pos4 % THREADS
                if ((pos4 & (THREADS - 1)) == tid) {
                    outf[c] = 1.0f;                          // ordered after own zero
                }
            }
        }
    }
}

extern "C" void kernel_launch(void* const* d_in, const int* in_sizes, int n_in,
                              void* d_out, int out_size) {
    // inputs: z (float32, unused), hID (int32), rID (int32), tID (int32)
    const int* hID = (const int*)d_in[1];
    const int* rID = (const int*)d_in[2];
    const int* tID = (const int*)d_in[3];

    onehot_kernel<<<NBLOCKS, THREADS>>>((float*)d_out, hID, rID, tID);
}